// round 12
// baseline (speedup 1.0000x reference)
#include <cuda_runtime.h>
#include <cuda_bf16.h>
#include <math.h>
#include <stdint.h>

#define N_ROWS 32768
#define DIM    256
#define KCODES 8192

#define BM      128
#define BNH     64                   // per-half k-tile width
#define HTILES  (KCODES / BNH / 2)   // 64 tiles per half
#define CAND_MAX 64
#define MARGIN  0.125f

// ---- scratch (device globals; no runtime allocation) ----
__device__ float  g_xnorm[N_ROWS];
__device__ float  g_enorm[KCODES];
__device__ int    g_bestIdx[N_ROWS];
__device__ float  g_embT[KCODES * DIM];                 // [K][D] fp32 for gather/rescore
__device__ __nv_bfloat16 g_Eh[KCODES * DIM];            // [K][D] bf16
__device__ __nv_bfloat16 g_Xh[(size_t)N_ROWS * DIM];    // [N][D] bf16
__device__ int    g_cand[(size_t)N_ROWS * CAND_MAX];
__device__ int    g_candCnt[N_ROWS];
__device__ double g_partial[512];

// =========================== helpers ===================================
__device__ __forceinline__ uint32_t s2u(const void* p) {
    uint32_t a;
    asm("{ .reg .u64 t; cvta.to.shared.u64 t, %1; cvt.u32.u64 %0, t; }" : "=r"(a) : "l"(p));
    return a;
}
__device__ __forceinline__ unsigned fenc(float f) {
    unsigned b = __float_as_uint(f);
    return (b & 0x80000000u) ? ~b : (b | 0x80000000u);
}
__device__ __forceinline__ float fdec(unsigned u) {
    return (u & 0x80000000u) ? __uint_as_float(u & 0x7FFFFFFFu) : __uint_as_float(~u);
}
__device__ __forceinline__ void ldsm4(uint32_t* d, uint32_t addr) {
    asm volatile("ldmatrix.sync.aligned.m8n8.x4.shared.b16 {%0,%1,%2,%3}, [%4];"
        : "=r"(d[0]), "=r"(d[1]), "=r"(d[2]), "=r"(d[3]) : "r"(addr));
}
__device__ __forceinline__ void mma_bf16(float* c, const uint32_t* a, const uint32_t* b) {
    asm volatile("mma.sync.aligned.m16n8k16.row.col.f32.bf16.bf16.f32 "
        "{%0,%1,%2,%3}, {%4,%5,%6,%7}, {%8,%9}, {%0,%1,%2,%3};"
        : "+f"(c[0]), "+f"(c[1]), "+f"(c[2]), "+f"(c[3])
        : "r"(a[0]), "r"(a[1]), "r"(a[2]), "r"(a[3]), "r"(b[0]), "r"(b[1]));
}
__device__ __forceinline__ void cpa16(uint32_t dst, const void* src) {
    asm volatile("cp.async.cg.shared.global [%0], [%1], 16;" :: "r"(dst), "l"(src));
}
#define CP_COMMIT() asm volatile("cp.async.commit_group;" ::: "memory")
#define CP_WAIT0()  asm volatile("cp.async.wait_group 0;" ::: "memory")
#define HBAR(h)     asm volatile("bar.sync %0, %1;" :: "r"(1 + (h)), "r"(256) : "memory")

// ======================= prep kernels ================================
// identical numerics to R3/R5 (sequential d loop per code)
__global__ void enorm_kernel(const float* __restrict__ E) {
    int k = blockIdx.x * blockDim.x + threadIdx.x;
    if (k >= KCODES) return;
    float s = 0.0f;
    #pragma unroll 8
    for (int d = 0; d < DIM; d++) { float v = E[d * KCODES + k]; s += v * v; }
    g_enorm[k] = s;
}

// E [D][K] -> embT fp32 [K][D] + Eh bf16 [K][D]  (fused)
__global__ void prepE_kernel(const float* __restrict__ E) {
    __shared__ float tile[32][33];
    int kBase = blockIdx.x * 32, dBase = blockIdx.y * 32;
    int tx = threadIdx.x, ty = threadIdx.y;   // (32, 8)
    #pragma unroll
    for (int i = 0; i < 32; i += 8)
        tile[ty + i][tx] = E[(size_t)(dBase + ty + i) * KCODES + kBase + tx];
    __syncthreads();
    #pragma unroll
    for (int i = 0; i < 32; i += 8) {
        float v = tile[tx][ty + i];
        size_t o = (size_t)(kBase + ty + i) * DIM + dBase + tx;
        g_embT[o] = v;
        g_Eh[o] = __float2bfloat16(v);
    }
}

// X: per-row ||x||^2 (R5 numerics) + bf16 convert, one X pass (fused)
__global__ void prepX_kernel(const float* __restrict__ X) {
    int gwarp = (blockIdx.x * blockDim.x + threadIdx.x) >> 5;
    int lane = threadIdx.x & 31;
    const float* xr = X + (size_t)gwarp * DIM;
    float4 a = *(const float4*)&xr[lane * 8];
    float4 b = *(const float4*)&xr[lane * 8 + 4];
    float s = a.x * a.x + a.y * a.y + a.z * a.z + a.w * a.w;
    s += b.x * b.x + b.y * b.y + b.z * b.z + b.w * b.w;
    #pragma unroll
    for (int off = 16; off > 0; off >>= 1) s += __shfl_xor_sync(0xFFFFFFFFu, s, off);
    if (lane == 0) g_xnorm[gwarp] = s;
    __nv_bfloat162 p0 = make_bfloat162(__float2bfloat16(a.x), __float2bfloat16(a.y));
    __nv_bfloat162 p1 = make_bfloat162(__float2bfloat16(a.z), __float2bfloat16(a.w));
    __nv_bfloat162 p2 = make_bfloat162(__float2bfloat16(b.x), __float2bfloat16(b.y));
    __nv_bfloat162 p3 = make_bfloat162(__float2bfloat16(b.z), __float2bfloat16(b.w));
    uint4 v = make_uint4(*(uint32_t*)&p0, *(uint32_t*)&p1, *(uint32_t*)&p2, *(uint32_t*)&p3);
    *(uint4*)&g_Xh[(size_t)gwarp * DIM + lane * 8] = v;
}

// ======================= phase 1: bf16 HMMA, two desynced halves ===========
// smem: A 64KB | B[half][buf] 4x32KB | rowMinKey[128] | rowCnt[128]
#define SMEM_BBASE 65536
#define BUFOFF(h, b) (SMEM_BBASE + ((h) * 2 + (b)) * 32768)
#define SMEM_KEY 196608
#define SMEM_CNT 197120
#define SMEM_P1  197632

__global__ __launch_bounds__(512, 1) void phase1_kernel() {
    extern __shared__ char smem[];
    uint32_t sb = s2u(smem);
    unsigned* rowMinKey = (unsigned*)(smem + SMEM_KEY);
    int*      rowCnt    = (int*)(smem + SMEM_CNT);

    int tid = threadIdx.x, lane = tid & 31, wid = tid >> 5;
    int half = wid >> 3;                 // 0 or 1 (two independent 8-warp groups)
    int wh = wid & 7, wm = wh >> 1, wn = wh & 1;  // 4x2 warp grid within half
    int g = lane >> 2, q = lane & 3;
    int htid = tid & 255;
    int rowBase = blockIdx.x * BM;

    if (tid < BM) { rowMinKey[tid] = 0xFFFFFFFFu; rowCnt[tid] = 0; }

    // ldmatrix row/chunk lane constants
    int rA = wm * 32 + (lane & 7) + ((lane >> 3) & 1) * 8;
    int caBit = lane >> 4;
    int rB = wn * 32 + (lane & 7) + ((lane >> 4) & 1) * 8;
    int cbBit = (lane >> 3) & 1;
    uint32_t aRowBase = sb + rA * 512;

    // ---- initial loads: A tile (all 512 threads) + each half's B tile 0 ----
    {
        const char* srcA = (const char*)g_Xh + (size_t)rowBase * 512;
        #pragma unroll
        for (int i = 0; i < 8; i++) {
            int lin = tid + i * 512;
            int r = lin >> 5, c = lin & 31;
            int gs = (c & ~7) | ((c ^ r) & 7);
            cpa16(sb + r * 512 + gs * 16, srcA + (size_t)r * 512 + c * 16);
        }
        const char* srcB = (const char*)g_Eh + (size_t)half * BNH * 512;
        uint32_t dstB = sb + BUFOFF(half, 0);
        #pragma unroll
        for (int i = 0; i < 8; i++) {
            int lin = htid + i * 256;      // 64 rows x 32 chunks = 2048
            int r = lin >> 5, c = lin & 31;
            int gs = (c & ~7) | ((c ^ r) & 7);
            cpa16(dstB + r * 512 + gs * 16, srcB + (size_t)r * 512 + c * 16);
        }
        CP_COMMIT();
        CP_WAIT0();
    }
    __syncthreads();

    int buf = 0;
    for (int t = 0; t < HTILES; t++) {
        int kbase = (2 * t + half) * BNH;

        // prefetch this half's next B tile
        if (t + 1 < HTILES) {
            const char* srcB = (const char*)g_Eh + (size_t)(2 * (t + 1) + half) * BNH * 512;
            uint32_t dstB = sb + BUFOFF(half, buf ^ 1);
            #pragma unroll
            for (int i = 0; i < 8; i++) {
                int lin = htid + i * 256;
                int r = lin >> 5, c = lin & 31;
                int gs = (c & ~7) | ((c ^ r) & 7);
                cpa16(dstB + r * 512 + gs * 16, srcB + (size_t)r * 512 + c * 16);
            }
            CP_COMMIT();
        }

        // hoist enorm loads: latency hides under the MMA loop
        float en[4][2];
        #pragma unroll
        for (int nt = 0; nt < 4; nt++)
            #pragma unroll
            for (int e = 0; e < 2; e++)
                en[nt][e] = __ldg(&g_enorm[kbase + wn * 32 + nt * 8 + q * 2 + e]);

        // ---- MMA mainloop over D=256 (16 ksteps) ----
        float acc[2][4][4];
        #pragma unroll
        for (int mt = 0; mt < 2; mt++)
            #pragma unroll
            for (int nt = 0; nt < 4; nt++)
                #pragma unroll
                for (int e = 0; e < 4; e++) acc[mt][nt][e] = 0.0f;

        uint32_t bRowBase = sb + BUFOFF(half, buf) + rB * 512;
        #pragma unroll
        for (int ks = 0; ks < 16; ks++) {
            uint32_t af0[4], af1[4], bfA[4], bfB[4];
            int cA = ks * 2 + caBit;
            int gsA = (cA & ~7) | ((cA ^ rA) & 7);
            uint32_t aAddr = aRowBase + gsA * 16;
            ldsm4(af0, aAddr);
            ldsm4(af1, aAddr + 16 * 512);
            int cB = ks * 2 + cbBit;
            int gsB = (cB & ~7) | ((cB ^ rB) & 7);
            uint32_t bAddr = bRowBase + gsB * 16;
            ldsm4(bfA, bAddr);
            ldsm4(bfB, bAddr + 16 * 512);
            mma_bf16(acc[0][0], af0, bfA + 0);
            mma_bf16(acc[0][1], af0, bfA + 2);
            mma_bf16(acc[0][2], af0, bfB + 0);
            mma_bf16(acc[0][3], af0, bfB + 2);
            mma_bf16(acc[1][0], af1, bfA + 0);
            mma_bf16(acc[1][1], af1, bfA + 2);
            mma_bf16(acc[1][2], af1, bfB + 0);
            mma_bf16(acc[1][3], af1, bfB + 2);
        }

        // ---- t=0 bootstrap: seed keys so first collect has finite thresholds
        if (t == 0) {
            #pragma unroll
            for (int mt = 0; mt < 2; mt++)
                #pragma unroll
                for (int h2 = 0; h2 < 2; h2++) {
                    int rl = wm * 32 + mt * 16 + g + h2 * 8;
                    float tm = INFINITY;
                    #pragma unroll
                    for (int nt = 0; nt < 4; nt++)
                        #pragma unroll
                        for (int e = 0; e < 2; e++)
                            tm = fminf(tm, fmaf(-2.0f, acc[mt][nt][h2 * 2 + e], en[nt][e]));
                    atomicMin(&rowMinKey[rl], fenc(tm));
                }
            HBAR(half);
        }

        // ---- single-pass epilogue: stale threshold, collect, rare min update
        #pragma unroll
        for (int mt = 0; mt < 2; mt++) {
            #pragma unroll
            for (int h2 = 0; h2 < 2; h2++) {
                int rl = wm * 32 + mt * 16 + g + h2 * 8;
                unsigned curKey = rowMinKey[rl];        // stale >= final min: safe
                float thr = fdec(curKey) + MARGIN;
                float tm = INFINITY;
                #pragma unroll
                for (int nt = 0; nt < 4; nt++)
                    #pragma unroll
                    for (int e = 0; e < 2; e++) {
                        float d = fmaf(-2.0f, acc[mt][nt][h2 * 2 + e], en[nt][e]);
                        tm = fminf(tm, d);
                        if (d < thr) {
                            int pos = atomicAdd(&rowCnt[rl], 1);
                            if (pos < CAND_MAX)
                                g_cand[(size_t)(rowBase + rl) * CAND_MAX + pos] =
                                    kbase + wn * 32 + nt * 8 + q * 2 + e;
                        }
                    }
                if (fenc(tm) < curKey) atomicMin(&rowMinKey[rl], fenc(tm));
            }
        }

        CP_WAIT0();
        HBAR(half);       // only this half syncs; other half keeps the tensor pipe busy
        buf ^= 1;
    }

    __syncthreads();
    if (tid < BM) g_candCnt[rowBase + tid] = rowCnt[tid];
}

// ======================= phase 2: exact fp32 rescore (R5 numerics) =========
__global__ __launch_bounds__(256) void rescore_kernel(const float* __restrict__ X) {
    int gw = (blockIdx.x * blockDim.x + threadIdx.x) >> 5;
    int lane = threadIdx.x & 31;
    const float* xr = X + (size_t)gw * DIM;
    float xn = g_xnorm[gw];
    int cnt = g_candCnt[gw];
    float bv = INFINITY;
    int   bi = 0x7FFFFFFF;

    if (cnt <= CAND_MAX) {
        float4 xa = *(const float4*)&xr[lane * 8];
        float4 xb = *(const float4*)&xr[lane * 8 + 4];
        for (int ci = 0; ci < cnt; ci++) {
            int k = g_cand[(size_t)gw * CAND_MAX + ci];
            const float* er = g_embT + (size_t)k * DIM;
            float4 ea = *(const float4*)&er[lane * 8];
            float4 eb = *(const float4*)&er[lane * 8 + 4];
            float d = xa.x * ea.x + xa.y * ea.y + xa.z * ea.z + xa.w * ea.w
                    + xb.x * eb.x + xb.y * eb.y + xb.z * eb.z + xb.w * eb.w;
            #pragma unroll
            for (int off = 16; off > 0; off >>= 1) d += __shfl_xor_sync(0xFFFFFFFFu, d, off);
            float dist = fmaf(-2.0f, d, xn) + g_enorm[k];
            if (dist < bv || (dist == bv && k < bi)) { bv = dist; bi = k; }
        }
    } else {
        // rare overflow: full exact scan
        for (int k = lane; k < KCODES; k += 32) {
            const float* er = g_embT + (size_t)k * DIM;
            float d = 0.0f;
            #pragma unroll 8
            for (int j = 0; j < DIM; j += 4) {
                float4 e4 = *(const float4*)&er[j];
                float4 x4 = *(const float4*)&xr[j];
                d += x4.x * e4.x + x4.y * e4.y + x4.z * e4.z + x4.w * e4.w;
            }
            float dist = fmaf(-2.0f, d, xn) + g_enorm[k];
            if (dist < bv || (dist == bv && k < bi)) { bv = dist; bi = k; }
        }
    }
    #pragma unroll
    for (int off = 16; off > 0; off >>= 1) {
        float ov = __shfl_xor_sync(0xFFFFFFFFu, bv, off);
        int   oi = __shfl_xor_sync(0xFFFFFFFFu, bi, off);
        if (ov < bv || (ov == bv && oi < bi)) { bv = ov; bi = oi; }
    }
    if (lane == 0) g_bestIdx[gw] = bi;
}

// ======================= gather + loss =====================================
__global__ __launch_bounds__(256) void gather_loss_kernel(const float* __restrict__ X,
                                                          float* __restrict__ out) {
    int base = blockIdx.x * 64;
    double lsum = 0.0;
    for (int e = threadIdx.x; e < 64 * 64; e += 256) {
        int r = e >> 6, d4 = e & 63;
        int row = base + r;
        int idx = g_bestIdx[row];
        float4 qv = *(const float4*)&g_embT[(size_t)idx * DIM + d4 * 4];
        float4 xv = *(const float4*)&X[(size_t)row * DIM + d4 * 4];
        *(float4*)&out[(size_t)row * DIM + d4 * 4] = qv;
        float dx = qv.x - xv.x, dy = qv.y - xv.y, dz = qv.z - xv.z, dw = qv.w - xv.w;
        lsum += (double)(dx * dx) + (double)(dy * dy) + (double)(dz * dz) + (double)(dw * dw);
    }
    __shared__ double sred[256];
    sred[threadIdx.x] = lsum;
    __syncthreads();
    #pragma unroll
    for (int off = 128; off > 0; off >>= 1) {
        if (threadIdx.x < off) sred[threadIdx.x] += sred[threadIdx.x + off];
        __syncthreads();
    }
    if (threadIdx.x == 0) g_partial[blockIdx.x] = sred[0];
}

__global__ void finalize_kernel(float* __restrict__ out, int lossPos) {
    __shared__ double sred[256];
    int t = threadIdx.x;
    sred[t] = g_partial[t] + g_partial[t + 256];
    __syncthreads();
    #pragma unroll
    for (int off = 128; off > 0; off >>= 1) {
        if (t < off) sred[t] += sred[t + off];
        __syncthreads();
    }
    if (t == 0) {
        float m = (float)(sred[0] / (double)((size_t)N_ROWS * DIM));
        out[lossPos] = m + 0.25f * m;
    }
}

// ===========================================================================
extern "C" void kernel_launch(void* const* d_in, const int* in_sizes, int n_in,
                              void* d_out, int out_size) {
    const float* X = (const float*)d_in[0];   // inputs   [64,512,256]
    const float* E = (const float*)d_in[1];   // embeddings [256,8192]
    float* out = (float*)d_out;

    cudaFuncSetAttribute(phase1_kernel,
                         cudaFuncAttributeMaxDynamicSharedMemorySize, SMEM_P1);

    enorm_kernel<<<KCODES / 256, 256>>>(E);
    prepE_kernel<<<dim3(KCODES / 32, DIM / 32), dim3(32, 8)>>>(E);
    prepX_kernel<<<N_ROWS / 8, 256>>>(X);
    phase1_kernel<<<N_ROWS / BM, 512, SMEM_P1>>>();
    rescore_kernel<<<N_ROWS / 8, 256>>>(X);
    gather_loss_kernel<<<512, 256>>>(X, out);
    finalize_kernel<<<1, 256>>>(out, out_size - 1);
}

// round 13
// speedup vs baseline: 1.0643x; 1.0643x over previous
#include <cuda_runtime.h>
#include <cuda_bf16.h>
#include <math.h>
#include <stdint.h>

#define N_ROWS 32768
#define DIM    256
#define KCODES 8192

#define BM      128
#define BNH     128                  // per-half k-tile width
#define HTILES  (KCODES / BNH / 2)   // 32 tiles per half
#define STAGESH (HTILES * 2)         // 64 pipeline stages per half (tile x dchunk)
#define CAND_MAX 64
#define MARGIN  0.125f

// ---- scratch (device globals; no runtime allocation) ----
__device__ float  g_xnorm[N_ROWS];
__device__ float  g_enorm[KCODES];
__device__ int    g_bestIdx[N_ROWS];
__device__ float  g_embT[KCODES * DIM];                 // [K][D] fp32 for gather/rescore
__device__ __nv_bfloat16 g_Eh[KCODES * DIM];            // [K][D] bf16
__device__ __nv_bfloat16 g_Xh[(size_t)N_ROWS * DIM];    // [N][D] bf16
__device__ int    g_cand[(size_t)N_ROWS * CAND_MAX];
__device__ int    g_candCnt[N_ROWS];
__device__ double g_partial[512];

// =========================== helpers ===================================
__device__ __forceinline__ uint32_t s2u(const void* p) {
    uint32_t a;
    asm("{ .reg .u64 t; cvta.to.shared.u64 t, %1; cvt.u32.u64 %0, t; }" : "=r"(a) : "l"(p));
    return a;
}
__device__ __forceinline__ unsigned fenc(float f) {
    unsigned b = __float_as_uint(f);
    return (b & 0x80000000u) ? ~b : (b | 0x80000000u);
}
__device__ __forceinline__ float fdec(unsigned u) {
    return (u & 0x80000000u) ? __uint_as_float(u & 0x7FFFFFFFu) : __uint_as_float(~u);
}
__device__ __forceinline__ void ldsm4(uint32_t* d, uint32_t addr) {
    asm volatile("ldmatrix.sync.aligned.m8n8.x4.shared.b16 {%0,%1,%2,%3}, [%4];"
        : "=r"(d[0]), "=r"(d[1]), "=r"(d[2]), "=r"(d[3]) : "r"(addr));
}
__device__ __forceinline__ void mma_bf16(float* c, const uint32_t* a, const uint32_t* b) {
    asm volatile("mma.sync.aligned.m16n8k16.row.col.f32.bf16.bf16.f32 "
        "{%0,%1,%2,%3}, {%4,%5,%6,%7}, {%8,%9}, {%0,%1,%2,%3};"
        : "+f"(c[0]), "+f"(c[1]), "+f"(c[2]), "+f"(c[3])
        : "r"(a[0]), "r"(a[1]), "r"(a[2]), "r"(a[3]), "r"(b[0]), "r"(b[1]));
}
__device__ __forceinline__ void cpa16(uint32_t dst, const void* src) {
    asm volatile("cp.async.cg.shared.global [%0], [%1], 16;" :: "r"(dst), "l"(src));
}
#define CP_COMMIT() asm volatile("cp.async.commit_group;" ::: "memory")
#define CP_WAIT0()  asm volatile("cp.async.wait_group 0;" ::: "memory")
#define HBAR(h)     asm volatile("bar.sync %0, %1;" :: "r"(1 + (h)), "r"(256) : "memory")

// ======================= prep kernels ================================
// identical numerics to R3/R5 (sequential d loop per code)
__global__ void enorm_kernel(const float* __restrict__ E) {
    int k = blockIdx.x * blockDim.x + threadIdx.x;
    if (k >= KCODES) return;
    float s = 0.0f;
    #pragma unroll 8
    for (int d = 0; d < DIM; d++) { float v = E[d * KCODES + k]; s += v * v; }
    g_enorm[k] = s;
}

// E [D][K] -> embT fp32 [K][D] + Eh bf16 [K][D]  (fused)
__global__ void prepE_kernel(const float* __restrict__ E) {
    __shared__ float tile[32][33];
    int kBase = blockIdx.x * 32, dBase = blockIdx.y * 32;
    int tx = threadIdx.x, ty = threadIdx.y;   // (32, 8)
    #pragma unroll
    for (int i = 0; i < 32; i += 8)
        tile[ty + i][tx] = E[(size_t)(dBase + ty + i) * KCODES + kBase + tx];
    __syncthreads();
    #pragma unroll
    for (int i = 0; i < 32; i += 8) {
        float v = tile[tx][ty + i];
        size_t o = (size_t)(kBase + ty + i) * DIM + dBase + tx;
        g_embT[o] = v;
        g_Eh[o] = __float2bfloat16(v);
    }
}

// X: per-row ||x||^2 (R5 numerics) + bf16 convert, one X pass (fused)
__global__ void prepX_kernel(const float* __restrict__ X) {
    int gwarp = (blockIdx.x * blockDim.x + threadIdx.x) >> 5;
    int lane = threadIdx.x & 31;
    const float* xr = X + (size_t)gwarp * DIM;
    float4 a = *(const float4*)&xr[lane * 8];
    float4 b = *(const float4*)&xr[lane * 8 + 4];
    float s = a.x * a.x + a.y * a.y + a.z * a.z + a.w * a.w;
    s += b.x * b.x + b.y * b.y + b.z * b.z + b.w * b.w;
    #pragma unroll
    for (int off = 16; off > 0; off >>= 1) s += __shfl_xor_sync(0xFFFFFFFFu, s, off);
    if (lane == 0) g_xnorm[gwarp] = s;
    __nv_bfloat162 p0 = make_bfloat162(__float2bfloat16(a.x), __float2bfloat16(a.y));
    __nv_bfloat162 p1 = make_bfloat162(__float2bfloat16(a.z), __float2bfloat16(a.w));
    __nv_bfloat162 p2 = make_bfloat162(__float2bfloat16(b.x), __float2bfloat16(b.y));
    __nv_bfloat162 p3 = make_bfloat162(__float2bfloat16(b.z), __float2bfloat16(b.w));
    uint4 v = make_uint4(*(uint32_t*)&p0, *(uint32_t*)&p1, *(uint32_t*)&p2, *(uint32_t*)&p3);
    *(uint4*)&g_Xh[(size_t)gwarp * DIM + lane * 8] = v;
}

// ======== phase 1: bf16 HMMA, two desynced halves, 32x64 warp tiles ========
// smem: A 64KB | B[half][buf] 4x32KB (128x128-d chunks) | rowMinKey | rowCnt
#define SMEM_BBASE 65536
#define BUFOFF(h, b) (SMEM_BBASE + ((h) * 2 + (b)) * 32768)
#define SMEM_KEY 196608
#define SMEM_CNT 197120
#define SMEM_P1  197632

__global__ __launch_bounds__(512, 1) void phase1_kernel() {
    extern __shared__ char smem[];
    uint32_t sb = s2u(smem);
    unsigned* rowMinKey = (unsigned*)(smem + SMEM_KEY);
    int*      rowCnt    = (int*)(smem + SMEM_CNT);

    int tid = threadIdx.x, lane = tid & 31, wid = tid >> 5;
    int half = wid >> 3;                          // two independent 8-warp groups
    int wh = wid & 7, wm = wh >> 1, wn = wh & 1;  // 4x2 grid, warp tile 32x64
    int g = lane >> 2, q = lane & 3;
    int htid = tid & 255;
    int rowBase = blockIdx.x * BM;

    if (tid < BM) { rowMinKey[tid] = 0xFFFFFFFFu; rowCnt[tid] = 0; }

    // ldmatrix lane constants
    int rA = wm * 32 + (lane & 7) + ((lane >> 3) & 1) * 8;
    int caBit = lane >> 4;
    int rB = wn * 64 + (lane & 7) + ((lane >> 4) & 1) * 8;   // code row within tile
    int cbBit = (lane >> 3) & 1;
    uint32_t aRowBase = sb + rA * 512;

    // ---- initial loads: A tile (512 thr) + each half's stage-0 B chunk ----
    {
        const char* srcA = (const char*)g_Xh + (size_t)rowBase * 512;
        #pragma unroll
        for (int i = 0; i < 8; i++) {
            int lin = tid + i * 512;
            int r = lin >> 5, c = lin & 31;
            int gs = (c & ~7) | ((c ^ r) & 7);
            cpa16(sb + r * 512 + gs * 16, srcA + (size_t)r * 512 + c * 16);
        }
        // stage 0: tile kt=half, dc=0
        const char* srcB = (const char*)g_Eh + (size_t)(half * BNH) * 512;
        uint32_t dstB = sb + BUFOFF(half, 0);
        #pragma unroll
        for (int i = 0; i < 8; i++) {
            int lin = htid + i * 256;      // 0..2047
            int r = lin >> 4, c = lin & 15;
            int gs = (c & ~7) | ((c ^ r) & 7);
            cpa16(dstB + r * 256 + gs * 16, srcB + (size_t)r * 512 + c * 16);
        }
        CP_COMMIT();
        CP_WAIT0();
    }
    __syncthreads();

    float acc[2][8][4];
    int buf = 0;
    for (int s = 0; s < STAGESH; s++) {
        int t = s >> 1, dc = s & 1;
        int kbase = (2 * t + half) * BNH;

        // prefetch next stage's 32KB B chunk
        if (s + 1 < STAGESH) {
            int t2 = (s + 1) >> 1, dc2 = (s + 1) & 1;
            const char* srcB = (const char*)g_Eh
                + (size_t)((2 * t2 + half) * BNH) * 512 + dc2 * 256;
            uint32_t dstB = sb + BUFOFF(half, buf ^ 1);
            #pragma unroll
            for (int i = 0; i < 8; i++) {
                int lin = htid + i * 256;
                int r = lin >> 4, c = lin & 15;
                int gs = (c & ~7) | ((c ^ r) & 7);
                cpa16(dstB + r * 256 + gs * 16, srcB + (size_t)r * 512 + c * 16);
            }
            CP_COMMIT();
        }

        if (dc == 0) {
            #pragma unroll
            for (int mt = 0; mt < 2; mt++)
                #pragma unroll
                for (int nt = 0; nt < 8; nt++)
                    #pragma unroll
                    for (int e = 0; e < 4; e++) acc[mt][nt][e] = 0.0f;
        }
        float en[8][2];
        if (dc == 1) {
            #pragma unroll
            for (int nt = 0; nt < 8; nt++)
                #pragma unroll
                for (int e = 0; e < 2; e++)
                    en[nt][e] = __ldg(&g_enorm[kbase + wn * 64 + nt * 8 + q * 2 + e]);
        }

        // ---- 8 ksteps over this D-chunk ----
        uint32_t bChunk = sb + BUFOFF(half, buf) + rB * 256;
        #pragma unroll
        for (int ks = 0; ks < 8; ks++) {
            uint32_t af0[4], af1[4], bf[4][4];
            int ksg = dc * 8 + ks;
            int cA = ksg * 2 + caBit;
            int gsA = (cA & ~7) | ((cA ^ rA) & 7);
            uint32_t aAddr = aRowBase + gsA * 16;
            ldsm4(af0, aAddr);
            ldsm4(af1, aAddr + 16 * 512);
            int cB = ks * 2 + cbBit;
            int gsB = (cB & ~7) | ((cB ^ rB) & 7);
            uint32_t bAddr = bChunk + gsB * 16;
            ldsm4(bf[0], bAddr);
            ldsm4(bf[1], bAddr + 16 * 256);
            ldsm4(bf[2], bAddr + 32 * 256);
            ldsm4(bf[3], bAddr + 48 * 256);
            #pragma unroll
            for (int nt = 0; nt < 8; nt++) {
                mma_bf16(acc[0][nt], af0, bf[nt >> 1] + 2 * (nt & 1));
                mma_bf16(acc[1][nt], af1, bf[nt >> 1] + 2 * (nt & 1));
            }
        }

        if (dc == 1) {
            // ---- bootstrap at first epilogue: seed keys so thr is finite ----
            if (t == 0) {
                #pragma unroll
                for (int mt = 0; mt < 2; mt++)
                    #pragma unroll
                    for (int h2 = 0; h2 < 2; h2++) {
                        int rl = wm * 32 + mt * 16 + g + h2 * 8;
                        float tm = INFINITY;
                        #pragma unroll
                        for (int nt = 0; nt < 8; nt++)
                            #pragma unroll
                            for (int e = 0; e < 2; e++)
                                tm = fminf(tm, fmaf(-2.0f, acc[mt][nt][h2 * 2 + e], en[nt][e]));
                        atomicMin(&rowMinKey[rl], fenc(tm));
                    }
                HBAR(half);
            }
            // ---- single-pass: stale threshold, collect, rare min update ----
            #pragma unroll
            for (int mt = 0; mt < 2; mt++) {
                #pragma unroll
                for (int h2 = 0; h2 < 2; h2++) {
                    int rl = wm * 32 + mt * 16 + g + h2 * 8;
                    unsigned curKey = rowMinKey[rl];       // stale >= final min: safe
                    float thr = fdec(curKey) + MARGIN;
                    float tm = INFINITY;
                    #pragma unroll
                    for (int nt = 0; nt < 8; nt++)
                        #pragma unroll
                        for (int e = 0; e < 2; e++) {
                            float d = fmaf(-2.0f, acc[mt][nt][h2 * 2 + e], en[nt][e]);
                            tm = fminf(tm, d);
                            if (d < thr) {
                                int pos = atomicAdd(&rowCnt[rl], 1);
                                if (pos < CAND_MAX)
                                    g_cand[(size_t)(rowBase + rl) * CAND_MAX + pos] =
                                        kbase + wn * 64 + nt * 8 + q * 2 + e;
                            }
                        }
                    if (fenc(tm) < curKey) atomicMin(&rowMinKey[rl], fenc(tm));
                }
            }
        }

        CP_WAIT0();
        HBAR(half);     // half-local; other half keeps the tensor pipe busy
        buf ^= 1;
    }

    __syncthreads();
    if (tid < BM) g_candCnt[rowBase + tid] = rowCnt[tid];
}

// ======================= phase 2: exact fp32 rescore (R5 numerics) =========
__global__ __launch_bounds__(256) void rescore_kernel(const float* __restrict__ X) {
    int gw = (blockIdx.x * blockDim.x + threadIdx.x) >> 5;
    int lane = threadIdx.x & 31;
    const float* xr = X + (size_t)gw * DIM;
    float xn = g_xnorm[gw];
    int cnt = g_candCnt[gw];
    float bv = INFINITY;
    int   bi = 0x7FFFFFFF;

    if (cnt <= CAND_MAX) {
        float4 xa = *(const float4*)&xr[lane * 8];
        float4 xb = *(const float4*)&xr[lane * 8 + 4];
        for (int ci = 0; ci < cnt; ci++) {
            int k = g_cand[(size_t)gw * CAND_MAX + ci];
            const float* er = g_embT + (size_t)k * DIM;
            float4 ea = *(const float4*)&er[lane * 8];
            float4 eb = *(const float4*)&er[lane * 8 + 4];
            float d = xa.x * ea.x + xa.y * ea.y + xa.z * ea.z + xa.w * ea.w
                    + xb.x * eb.x + xb.y * eb.y + xb.z * eb.z + xb.w * eb.w;
            #pragma unroll
            for (int off = 16; off > 0; off >>= 1) d += __shfl_xor_sync(0xFFFFFFFFu, d, off);
            float dist = fmaf(-2.0f, d, xn) + g_enorm[k];
            if (dist < bv || (dist == bv && k < bi)) { bv = dist; bi = k; }
        }
    } else {
        // rare overflow: full exact scan
        for (int k = lane; k < KCODES; k += 32) {
            const float* er = g_embT + (size_t)k * DIM;
            float d = 0.0f;
            #pragma unroll 8
            for (int j = 0; j < DIM; j += 4) {
                float4 e4 = *(const float4*)&er[j];
                float4 x4 = *(const float4*)&xr[j];
                d += x4.x * e4.x + x4.y * e4.y + x4.z * e4.z + x4.w * e4.w;
            }
            float dist = fmaf(-2.0f, d, xn) + g_enorm[k];
            if (dist < bv || (dist == bv && k < bi)) { bv = dist; bi = k; }
        }
    }
    #pragma unroll
    for (int off = 16; off > 0; off >>= 1) {
        float ov = __shfl_xor_sync(0xFFFFFFFFu, bv, off);
        int   oi = __shfl_xor_sync(0xFFFFFFFFu, bi, off);
        if (ov < bv || (ov == bv && oi < bi)) { bv = ov; bi = oi; }
    }
    if (lane == 0) g_bestIdx[gw] = bi;
}

// ======================= gather + loss =====================================
__global__ __launch_bounds__(256) void gather_loss_kernel(const float* __restrict__ X,
                                                          float* __restrict__ out) {
    int base = blockIdx.x * 64;
    double lsum = 0.0;
    for (int e = threadIdx.x; e < 64 * 64; e += 256) {
        int r = e >> 6, d4 = e & 63;
        int row = base + r;
        int idx = g_bestIdx[row];
        float4 qv = *(const float4*)&g_embT[(size_t)idx * DIM + d4 * 4];
        float4 xv = *(const float4*)&X[(size_t)row * DIM + d4 * 4];
        *(float4*)&out[(size_t)row * DIM + d4 * 4] = qv;
        float dx = qv.x - xv.x, dy = qv.y - xv.y, dz = qv.z - xv.z, dw = qv.w - xv.w;
        lsum += (double)(dx * dx) + (double)(dy * dy) + (double)(dz * dz) + (double)(dw * dw);
    }
    __shared__ double sred[256];
    sred[threadIdx.x] = lsum;
    __syncthreads();
    #pragma unroll
    for (int off = 128; off > 0; off >>= 1) {
        if (threadIdx.x < off) sred[threadIdx.x] += sred[threadIdx.x + off];
        __syncthreads();
    }
    if (threadIdx.x == 0) g_partial[blockIdx.x] = sred[0];
}

__global__ void finalize_kernel(float* __restrict__ out, int lossPos) {
    __shared__ double sred[256];
    int t = threadIdx.x;
    sred[t] = g_partial[t] + g_partial[t + 256];
    __syncthreads();
    #pragma unroll
    for (int off = 128; off > 0; off >>= 1) {
        if (t < off) sred[t] += sred[t + off];
        __syncthreads();
    }
    if (t == 0) {
        float m = (float)(sred[0] / (double)((size_t)N_ROWS * DIM));
        out[lossPos] = m + 0.25f * m;
    }
}

// ===========================================================================
extern "C" void kernel_launch(void* const* d_in, const int* in_sizes, int n_in,
                              void* d_out, int out_size) {
    const float* X = (const float*)d_in[0];   // inputs   [64,512,256]
    const float* E = (const float*)d_in[1];   // embeddings [256,8192]
    float* out = (float*)d_out;

    cudaFuncSetAttribute(phase1_kernel,
                         cudaFuncAttributeMaxDynamicSharedMemorySize, SMEM_P1);

    enorm_kernel<<<KCODES / 256, 256>>>(E);
    prepE_kernel<<<dim3(KCODES / 32, DIM / 32), dim3(32, 8)>>>(E);
    prepX_kernel<<<N_ROWS / 8, 256>>>(X);
    phase1_kernel<<<N_ROWS / BM, 512, SMEM_P1>>>();
    rescore_kernel<<<N_ROWS / 8, 256>>>(X);
    gather_loss_kernel<<<512, 256>>>(X, out);
    finalize_kernel<<<1, 256>>>(out, out_size - 1);
}

// round 15
// speedup vs baseline: 1.1233x; 1.0554x over previous
#include <cuda_runtime.h>
#include <cuda_bf16.h>
#include <math.h>
#include <stdint.h>

#define N_ROWS 32768
#define DIM    256
#define KCODES 8192

#define BM      128
#define BNH     128                  // per-half k-tile width
#define HTILES  (KCODES / BNH / 2)   // 32 tiles per half
#define STAGESH (HTILES * 2)         // 64 pipeline stages per half (tile x dchunk)
#define CAND_MAX 64
#define MARGIN  0.125f

// ---- scratch (device globals; no runtime allocation) ----
__device__ float  g_xnorm[N_ROWS];
__device__ float  g_enorm[KCODES];
__device__ float  g_embT[KCODES * DIM];                 // [K][D] fp32 for gather/rescore
__device__ __nv_bfloat16 g_Eh[KCODES * DIM];            // [K][D] bf16
__device__ __nv_bfloat16 g_Xh[(size_t)N_ROWS * DIM];    // [N][D] bf16
__device__ int    g_cand[(size_t)N_ROWS * CAND_MAX];
__device__ int    g_candCnt[N_ROWS];
__device__ double g_partial[N_ROWS];                    // one partial per row (1 warp/row)

// =========================== helpers ===================================
__device__ __forceinline__ uint32_t s2u(const void* p) {
    uint32_t a;
    asm("{ .reg .u64 t; cvta.to.shared.u64 t, %1; cvt.u32.u64 %0, t; }" : "=r"(a) : "l"(p));
    return a;
}
__device__ __forceinline__ unsigned fenc(float f) {
    unsigned b = __float_as_uint(f);
    return (b & 0x80000000u) ? ~b : (b | 0x80000000u);
}
__device__ __forceinline__ float fdec(unsigned u) {
    return (u & 0x80000000u) ? __uint_as_float(u & 0x7FFFFFFFu) : __uint_as_float(~u);
}
__device__ __forceinline__ void ldsm4(uint32_t* d, uint32_t addr) {
    asm volatile("ldmatrix.sync.aligned.m8n8.x4.shared.b16 {%0,%1,%2,%3}, [%4];"
        : "=r"(d[0]), "=r"(d[1]), "=r"(d[2]), "=r"(d[3]) : "r"(addr));
}
__device__ __forceinline__ void mma_bf16(float* c, const uint32_t* a, const uint32_t* b) {
    asm volatile("mma.sync.aligned.m16n8k16.row.col.f32.bf16.bf16.f32 "
        "{%0,%1,%2,%3}, {%4,%5,%6,%7}, {%8,%9}, {%0,%1,%2,%3};"
        : "+f"(c[0]), "+f"(c[1]), "+f"(c[2]), "+f"(c[3])
        : "r"(a[0]), "r"(a[1]), "r"(a[2]), "r"(a[3]), "r"(b[0]), "r"(b[1]));
}
__device__ __forceinline__ void cpa16(uint32_t dst, const void* src) {
    asm volatile("cp.async.cg.shared.global [%0], [%1], 16;" :: "r"(dst), "l"(src));
}
#define CP_COMMIT() asm volatile("cp.async.commit_group;" ::: "memory")
#define CP_WAIT0()  asm volatile("cp.async.wait_group 0;" ::: "memory")
#define HBAR(h)     asm volatile("bar.sync %0, %1;" :: "r"(1 + (h)), "r"(256) : "memory")

// ======================= fused prep kernel ================================
// blockIdx.x ranges: [0,32) enorm | [32,2080) prepE | [2080,6176) prepX
// each role's inner numerics byte-identical to the R13 kernels.
#define PREP_ENORM 32
#define PREP_E     2048
#define PREP_X     4096
#define PREP_GRID  (PREP_ENORM + PREP_E + PREP_X)

__global__ __launch_bounds__(256) void prep_kernel(const float* __restrict__ X,
                                                   const float* __restrict__ E) {
    int b = blockIdx.x;
    if (b < PREP_ENORM) {
        // ---- enorm: sequential d loop per code (R3/R5 numerics) ----
        int k = b * 256 + threadIdx.x;
        float s = 0.0f;
        #pragma unroll 8
        for (int d = 0; d < DIM; d++) { float v = E[(size_t)d * KCODES + k]; s += v * v; }
        g_enorm[k] = s;
    } else if (b < PREP_ENORM + PREP_E) {
        // ---- prepE: E [D][K] -> embT fp32 [K][D] + Eh bf16 [K][D] ----
        __shared__ float tile[32][33];
        int idx = b - PREP_ENORM;
        int kBase = (idx & 255) * 32, dBase = (idx >> 8) * 32;
        int tx = threadIdx.x & 31, ty = threadIdx.x >> 5;   // (32, 8)
        #pragma unroll
        for (int i = 0; i < 32; i += 8)
            tile[ty + i][tx] = E[(size_t)(dBase + ty + i) * KCODES + kBase + tx];
        __syncthreads();
        #pragma unroll
        for (int i = 0; i < 32; i += 8) {
            float v = tile[tx][ty + i];
            size_t o = (size_t)(kBase + ty + i) * DIM + dBase + tx;
            g_embT[o] = v;
            g_Eh[o] = __float2bfloat16(v);
        }
    } else {
        // ---- prepX: per-row ||x||^2 + bf16 convert (R5 numerics) ----
        int idx = b - (PREP_ENORM + PREP_E);
        int gwarp = (idx * 256 + threadIdx.x) >> 5;
        int lane = threadIdx.x & 31;
        const float* xr = X + (size_t)gwarp * DIM;
        float4 a = *(const float4*)&xr[lane * 8];
        float4 bb = *(const float4*)&xr[lane * 8 + 4];
        float s = a.x * a.x + a.y * a.y + a.z * a.z + a.w * a.w;
        s += bb.x * bb.x + bb.y * bb.y + bb.z * bb.z + bb.w * bb.w;
        #pragma unroll
        for (int off = 16; off > 0; off >>= 1) s += __shfl_xor_sync(0xFFFFFFFFu, s, off);
        if (lane == 0) g_xnorm[gwarp] = s;
        __nv_bfloat162 p0 = make_bfloat162(__float2bfloat16(a.x), __float2bfloat16(a.y));
        __nv_bfloat162 p1 = make_bfloat162(__float2bfloat16(a.z), __float2bfloat16(a.w));
        __nv_bfloat162 p2 = make_bfloat162(__float2bfloat16(bb.x), __float2bfloat16(bb.y));
        __nv_bfloat162 p3 = make_bfloat162(__float2bfloat16(bb.z), __float2bfloat16(bb.w));
        uint4 v = make_uint4(*(uint32_t*)&p0, *(uint32_t*)&p1, *(uint32_t*)&p2, *(uint32_t*)&p3);
        *(uint4*)&g_Xh[(size_t)gwarp * DIM + lane * 8] = v;
    }
}

// ======== phase 1: bf16 HMMA, two desynced halves, 32x64 warp tiles ========
// (unchanged from R13)
#define SMEM_BBASE 65536
#define BUFOFF(h, b) (SMEM_BBASE + ((h) * 2 + (b)) * 32768)
#define SMEM_KEY 196608
#define SMEM_CNT 197120
#define SMEM_P1  197632

__global__ __launch_bounds__(512, 1) void phase1_kernel() {
    extern __shared__ char smem[];
    uint32_t sb = s2u(smem);
    unsigned* rowMinKey = (unsigned*)(smem + SMEM_KEY);
    int*      rowCnt    = (int*)(smem + SMEM_CNT);

    int tid = threadIdx.x, lane = tid & 31, wid = tid >> 5;
    int half = wid >> 3;
    int wh = wid & 7, wm = wh >> 1, wn = wh & 1;
    int g = lane >> 2, q = lane & 3;
    int htid = tid & 255;
    int rowBase = blockIdx.x * BM;

    if (tid < BM) { rowMinKey[tid] = 0xFFFFFFFFu; rowCnt[tid] = 0; }

    int rA = wm * 32 + (lane & 7) + ((lane >> 3) & 1) * 8;
    int caBit = lane >> 4;
    int rB = wn * 64 + (lane & 7) + ((lane >> 4) & 1) * 8;
    int cbBit = (lane >> 3) & 1;
    uint32_t aRowBase = sb + rA * 512;

    {
        const char* srcA = (const char*)g_Xh + (size_t)rowBase * 512;
        #pragma unroll
        for (int i = 0; i < 8; i++) {
            int lin = tid + i * 512;
            int r = lin >> 5, c = lin & 31;
            int gs = (c & ~7) | ((c ^ r) & 7);
            cpa16(sb + r * 512 + gs * 16, srcA + (size_t)r * 512 + c * 16);
        }
        const char* srcB = (const char*)g_Eh + (size_t)(half * BNH) * 512;
        uint32_t dstB = sb + BUFOFF(half, 0);
        #pragma unroll
        for (int i = 0; i < 8; i++) {
            int lin = htid + i * 256;
            int r = lin >> 4, c = lin & 15;
            int gs = (c & ~7) | ((c ^ r) & 7);
            cpa16(dstB + r * 256 + gs * 16, srcB + (size_t)r * 512 + c * 16);
        }
        CP_COMMIT();
        CP_WAIT0();
    }
    __syncthreads();

    float acc[2][8][4];
    int buf = 0;
    for (int s = 0; s < STAGESH; s++) {
        int t = s >> 1, dc = s & 1;
        int kbase = (2 * t + half) * BNH;

        if (s + 1 < STAGESH) {
            int t2 = (s + 1) >> 1, dc2 = (s + 1) & 1;
            const char* srcB = (const char*)g_Eh
                + (size_t)((2 * t2 + half) * BNH) * 512 + dc2 * 256;
            uint32_t dstB = sb + BUFOFF(half, buf ^ 1);
            #pragma unroll
            for (int i = 0; i < 8; i++) {
                int lin = htid + i * 256;
                int r = lin >> 4, c = lin & 15;
                int gs = (c & ~7) | ((c ^ r) & 7);
                cpa16(dstB + r * 256 + gs * 16, srcB + (size_t)r * 512 + c * 16);
            }
            CP_COMMIT();
        }

        if (dc == 0) {
            #pragma unroll
            for (int mt = 0; mt < 2; mt++)
                #pragma unroll
                for (int nt = 0; nt < 8; nt++)
                    #pragma unroll
                    for (int e = 0; e < 4; e++) acc[mt][nt][e] = 0.0f;
        }
        float en[8][2];
        if (dc == 1) {
            #pragma unroll
            for (int nt = 0; nt < 8; nt++)
                #pragma unroll
                for (int e = 0; e < 2; e++)
                    en[nt][e] = __ldg(&g_enorm[kbase + wn * 64 + nt * 8 + q * 2 + e]);
        }

        uint32_t bChunk = sb + BUFOFF(half, buf) + rB * 256;
        #pragma unroll
        for (int ks = 0; ks < 8; ks++) {
            uint32_t af0[4], af1[4], bf[4][4];
            int ksg = dc * 8 + ks;
            int cA = ksg * 2 + caBit;
            int gsA = (cA & ~7) | ((cA ^ rA) & 7);
            uint32_t aAddr = aRowBase + gsA * 16;
            ldsm4(af0, aAddr);
            ldsm4(af1, aAddr + 16 * 512);
            int cB = ks * 2 + cbBit;
            int gsB = (cB & ~7) | ((cB ^ rB) & 7);
            uint32_t bAddr = bChunk + gsB * 16;
            ldsm4(bf[0], bAddr);
            ldsm4(bf[1], bAddr + 16 * 256);
            ldsm4(bf[2], bAddr + 32 * 256);
            ldsm4(bf[3], bAddr + 48 * 256);
            #pragma unroll
            for (int nt = 0; nt < 8; nt++) {
                mma_bf16(acc[0][nt], af0, bf[nt >> 1] + 2 * (nt & 1));
                mma_bf16(acc[1][nt], af1, bf[nt >> 1] + 2 * (nt & 1));
            }
        }

        if (dc == 1) {
            if (t == 0) {
                #pragma unroll
                for (int mt = 0; mt < 2; mt++)
                    #pragma unroll
                    for (int h2 = 0; h2 < 2; h2++) {
                        int rl = wm * 32 + mt * 16 + g + h2 * 8;
                        float tm = INFINITY;
                        #pragma unroll
                        for (int nt = 0; nt < 8; nt++)
                            #pragma unroll
                            for (int e = 0; e < 2; e++)
                                tm = fminf(tm, fmaf(-2.0f, acc[mt][nt][h2 * 2 + e], en[nt][e]));
                        atomicMin(&rowMinKey[rl], fenc(tm));
                    }
                HBAR(half);
            }
            #pragma unroll
            for (int mt = 0; mt < 2; mt++) {
                #pragma unroll
                for (int h2 = 0; h2 < 2; h2++) {
                    int rl = wm * 32 + mt * 16 + g + h2 * 8;
                    unsigned curKey = rowMinKey[rl];       // stale >= final min: safe
                    float thr = fdec(curKey) + MARGIN;
                    float tm = INFINITY;
                    #pragma unroll
                    for (int nt = 0; nt < 8; nt++)
                        #pragma unroll
                        for (int e = 0; e < 2; e++) {
                            float d = fmaf(-2.0f, acc[mt][nt][h2 * 2 + e], en[nt][e]);
                            tm = fminf(tm, d);
                            if (d < thr) {
                                int pos = atomicAdd(&rowCnt[rl], 1);
                                if (pos < CAND_MAX)
                                    g_cand[(size_t)(rowBase + rl) * CAND_MAX + pos] =
                                        kbase + wn * 64 + nt * 8 + q * 2 + e;
                            }
                        }
                    if (fenc(tm) < curKey) atomicMin(&rowMinKey[rl], fenc(tm));
                }
            }
        }

        CP_WAIT0();
        HBAR(half);
        buf ^= 1;
    }

    __syncthreads();
    if (tid < BM) g_candCnt[rowBase + tid] = rowCnt[tid];
}

// ===== phase 2: exact fp32 rescore + fused gather/output/loss-partial ======
__global__ __launch_bounds__(256) void rescore_gather_kernel(const float* __restrict__ X,
                                                             float* __restrict__ out) {
    int gw = (blockIdx.x * blockDim.x + threadIdx.x) >> 5;   // one warp per row
    int lane = threadIdx.x & 31;
    const float* xr = X + (size_t)gw * DIM;
    float xn = g_xnorm[gw];
    int cnt = g_candCnt[gw];
    float bv = INFINITY;
    int   bi = 0x7FFFFFFF;

    if (cnt <= CAND_MAX) {
        float4 xa = *(const float4*)&xr[lane * 8];
        float4 xb = *(const float4*)&xr[lane * 8 + 4];
        for (int ci = 0; ci < cnt; ci++) {
            int k = g_cand[(size_t)gw * CAND_MAX + ci];
            const float* er = g_embT + (size_t)k * DIM;
            float4 ea = *(const float4*)&er[lane * 8];
            float4 eb = *(const float4*)&er[lane * 8 + 4];
            float d = xa.x * ea.x + xa.y * ea.y + xa.z * ea.z + xa.w * ea.w
                    + xb.x * eb.x + xb.y * eb.y + xb.z * eb.z + xb.w * eb.w;
            #pragma unroll
            for (int off = 16; off > 0; off >>= 1) d += __shfl_xor_sync(0xFFFFFFFFu, d, off);
            float dist = fmaf(-2.0f, d, xn) + g_enorm[k];
            if (dist < bv || (dist == bv && k < bi)) { bv = dist; bi = k; }
        }
    } else {
        // rare overflow: full exact scan
        for (int k = lane; k < KCODES; k += 32) {
            const float* er = g_embT + (size_t)k * DIM;
            float d = 0.0f;
            #pragma unroll 8
            for (int j = 0; j < DIM; j += 4) {
                float4 e4 = *(const float4*)&er[j];
                float4 x4 = *(const float4*)&xr[j];
                d += x4.x * e4.x + x4.y * e4.y + x4.z * e4.z + x4.w * e4.w;
            }
            float dist = fmaf(-2.0f, d, xn) + g_enorm[k];
            if (dist < bv || (dist == bv && k < bi)) { bv = dist; bi = k; }
        }
    }
    #pragma unroll
    for (int off = 16; off > 0; off >>= 1) {
        float ov = __shfl_xor_sync(0xFFFFFFFFu, bv, off);
        int   oi = __shfl_xor_sync(0xFFFFFFFFu, bi, off);
        if (ov < bv || (ov == bv && oi < bi)) { bv = ov; bi = oi; }
    }
    // butterfly leaves (bv, bi) uniform across the warp: gather + output + loss
    {
        const float* er = g_embT + (size_t)bi * DIM;
        float4 qa = *(const float4*)&er[lane * 8];
        float4 qb = *(const float4*)&er[lane * 8 + 4];
        float4 xa = *(const float4*)&xr[lane * 8];
        float4 xb = *(const float4*)&xr[lane * 8 + 4];
        *(float4*)&out[(size_t)gw * DIM + lane * 8] = qa;
        *(float4*)&out[(size_t)gw * DIM + lane * 8 + 4] = qb;
        float d0 = qa.x - xa.x, d1 = qa.y - xa.y, d2 = qa.z - xa.z, d3 = qa.w - xa.w;
        float d4 = qb.x - xb.x, d5 = qb.y - xb.y, d6 = qb.z - xb.z, d7 = qb.w - xb.w;
        double ls = (double)(d0 * d0) + (double)(d1 * d1)
                  + (double)(d2 * d2) + (double)(d3 * d3)
                  + (double)(d4 * d4) + (double)(d5 * d5)
                  + (double)(d6 * d6) + (double)(d7 * d7);
        #pragma unroll
        for (int off = 16; off > 0; off >>= 1)
            ls += __shfl_xor_sync(0xFFFFFFFFu, ls, off);
        if (lane == 0) g_partial[gw] = ls;
    }
}

// ======================= finalize: loss scalar =============================
__global__ __launch_bounds__(256) void finalize_kernel(float* __restrict__ out, int lossPos) {
    __shared__ double sred[256];
    int t = threadIdx.x;
    double s = 0.0;
    for (int i = t; i < N_ROWS; i += 256) s += g_partial[i];
    sred[t] = s;
    __syncthreads();
    #pragma unroll
    for (int off = 128; off > 0; off >>= 1) {
        if (t < off) sred[t] += sred[t + off];
        __syncthreads();
    }
    if (t == 0) {
        float m = (float)(sred[0] / (double)((size_t)N_ROWS * DIM));
        out[lossPos] = m + 0.25f * m;
    }
}

// ===========================================================================
extern "C" void kernel_launch(void* const* d_in, const int* in_sizes, int n_in,
                              void* d_out, int out_size) {
    const float* X = (const float*)d_in[0];   // inputs   [64,512,256]
    const float* E = (const float*)d_in[1];   // embeddings [256,8192]
    float* out = (float*)d_out;

    cudaFuncSetAttribute(phase1_kernel,
                         cudaFuncAttributeMaxDynamicSharedMemorySize, SMEM_P1);

    prep_kernel<<<PREP_GRID, 256>>>(X, E);
    phase1_kernel<<<N_ROWS / BM, 512, SMEM_P1>>>();
    rescore_gather_kernel<<<N_ROWS / 8, 256>>>(X, out);
    finalize_kernel<<<1, 256>>>(out, out_size - 1);
}